// round 14
// baseline (speedup 1.0000x reference)
#include <cuda_runtime.h>
#include <cuda_bf16.h>
#include <cuda_fp16.h>
#include <cstdint>
#include <math.h>

#define H 1024
#define VOCAB 32000
#define NTILES 250   // 32000/128

// ============================ helpers ============================
__device__ __forceinline__ uint32_t smem_to_u32(const void* smem_ptr) {
    uint32_t addr;
    asm("{ .reg .u64 tmp; cvta.to.shared.u64 tmp, %1; cvt.u32.u64 %0, tmp; }"
        : "=r"(addr) : "l"(smem_ptr));
    return addr;
}

#define SMEM_SWIZZLE_128B(byte_offset) \
    ((byte_offset) ^ (((byte_offset) >> 3) & 0x70))

__device__ __forceinline__ void cp_async_16(uint32_t smem_addr, const void* gmem) {
    asm volatile("cp.async.cg.shared.global [%0], [%1], 16;" :: "r"(smem_addr), "l"(gmem));
}
__device__ __forceinline__ void cp_async_commit() {
    asm volatile("cp.async.commit_group;" ::: "memory");
}
template <int N>
__device__ __forceinline__ void cp_async_wait() {
    asm volatile("cp.async.wait_group %0;" :: "n"(N) : "memory");
}

__device__ __forceinline__ void ldmatrix_x4(uint32_t& r0, uint32_t& r1, uint32_t& r2, uint32_t& r3,
                                            uint32_t addr) {
    asm volatile("ldmatrix.sync.aligned.m8n8.x4.shared.b16 {%0,%1,%2,%3}, [%4];"
                 : "=r"(r0), "=r"(r1), "=r"(r2), "=r"(r3) : "r"(addr));
}

__device__ __forceinline__ void mma_bf16(float* d, const uint32_t* a, const uint32_t* b) {
    asm volatile(
        "mma.sync.aligned.m16n8k16.row.col.f32.bf16.bf16.f32 "
        "{%0,%1,%2,%3}, {%4,%5,%6,%7}, {%8,%9}, {%0,%1,%2,%3};"
        : "+f"(d[0]), "+f"(d[1]), "+f"(d[2]), "+f"(d[3])
        : "r"(a[0]), "r"(a[1]), "r"(a[2]), "r"(a[3]), "r"(b[0]), "r"(b[1]));
}

__device__ __forceinline__ float fast_sigmoid(float x) {
    return __fdividef(1.f, 1.f + __expf(-x));
}
__device__ __forceinline__ float fast_tanh(float x) {
    float xc = fminf(fmaxf(x, -15.f), 15.f);
    float t = __expf(2.f * xc);
    return __fdividef(t - 1.f, t + 1.f);
}

// ============================ device scratch ============================
__device__ __align__(16) float          g_hbuf0[H * H];
__device__ __align__(16) float          g_hbuf1[H * H];
__device__ __align__(16) __nv_bfloat16  g_hhi0[H * H];
__device__ __align__(16) __nv_bfloat16  g_hhi1[H * H];
__device__ __align__(16) __nv_bfloat16  g_whi[6144 * H];
__device__ __align__(16) __nv_bfloat16  g_w_bf16[(size_t)VOCAB * H];
__device__ __align__(16) __half         g_logits[(size_t)H * VOCAB];
__device__ float g_pmax[H * NTILES];
__device__ float g_psum[H * NTILES];
__device__ float g_lse[H];

// ============================ Wout conversion (side stream) ============================
__global__ __launch_bounds__(256)
void wout_conv_kernel(const float* __restrict__ W, __nv_bfloat16* __restrict__ wb) {
    for (int i4 = blockIdx.x * 256 + threadIdx.x; i4 < 8192000; i4 += gridDim.x * 256) {
        float4 v = __ldcs((const float4*)W + i4);
        __nv_bfloat162 h2[2];
        h2[0] = __floats2bfloat162_rn(v.x, v.y);
        h2[1] = __floats2bfloat162_rn(v.z, v.w);
        uint32_t u0 = *(uint32_t*)&h2[0];
        uint32_t u1 = *(uint32_t*)&h2[1];
        __stcs((uint32_t*)(wb + i4 * 4),     u0);
        __stcs((uint32_t*)(wb + i4 * 4 + 2), u1);
    }
}

// ============================ Whh -> bf16 conversion chunk (background in d0-d2) ============================
__device__ __forceinline__ void wsplit_chunk(const float* __restrict__ Wl, const float* __restrict__ Wr,
                                             __nv_bfloat16* __restrict__ whi,
                                             int conv_base4, int cbid, int tid) {
#pragma unroll
    for (int u = 0; u < 4; ++u) {
        int i4 = conv_base4 + cbid * 1024 + u * 256 + tid;
        int i = i4 * 4;
        const float* src = (i < 3072 * H) ? Wl : Wr;
        int off = (i < 3072 * H) ? i : i - 3072 * H;
        float4 v = *(const float4*)(src + off);
        __nv_bfloat162 hi2[2];
        hi2[0] = __floats2bfloat162_rn(v.x, v.y);
        hi2[1] = __floats2bfloat162_rn(v.z, v.w);
        *(uint32_t*)(whi + i)     = *(uint32_t*)&hi2[0];
        *(uint32_t*)(whi + i + 2) = *(uint32_t*)&hi2[1];
    }
}

// ============================ K-split GEMV, fp32 W (d0-d2) ============================
template <int NN>
__global__ __launch_bounds__(256)
void gemv_split_kernel(const float* __restrict__ h_in,
                       const float* __restrict__ Whh_l, const float* __restrict__ bih_l,
                       const float* __restrict__ bhh_l,
                       const float* __restrict__ Whh_r, const float* __restrict__ bih_r,
                       const float* __restrict__ bhh_r,
                       float* __restrict__ h_out, __nv_bfloat16* __restrict__ hi_out,
                       __nv_bfloat16* __restrict__ whi,
                       int conv_base4) {
    const int tid = threadIdx.x;
    if (blockIdx.x >= 512) {
        wsplit_chunk(Whh_l, Whh_r, whi, conv_base4, blockIdx.x - 512, tid);
        return;
    }

    extern __shared__ float sh[];
    float* smP = sh + NN * 1024;

    const int wid = tid >> 5, lane = tid & 31;
    const int pair = blockIdx.x * 4 + (wid >> 1);
    const int khalf = wid & 1;
    const int side = pair >> 10;
    const int j = pair & 1023;
    const float* __restrict__ W = side ? Whh_r : Whh_l;
    const float* wr = W + (size_t)j * 1024 + khalf * 512;
    const float* wz = W + (size_t)(1024 + j) * 1024 + khalf * 512;
    const float* wn = W + (size_t)(2048 + j) * 1024 + khalf * 512;
    const float* shh = sh + khalf * 512;

    // W prefetch (in flight during h staging)
    float4 c0r = *(const float4*)(wr + lane * 4);
    float4 c0z = *(const float4*)(wz + lane * 4);
    float4 c0n = *(const float4*)(wn + lane * 4);
    float4 c1r = *(const float4*)(wr + 128 + lane * 4);
    float4 c1z = *(const float4*)(wz + 128 + lane * 4);
    float4 c1n = *(const float4*)(wn + 128 + lane * 4);

    for (int i = tid; i < NN * 1024; i += 256) sh[i] = h_in[i];
    __syncthreads();

    float ar[NN], az[NN], an[NN];
#pragma unroll
    for (int n = 0; n < NN; ++n) { ar[n] = 0.f; az[n] = 0.f; an[n] = 0.f; }

#pragma unroll 1
    for (int c = 0; c < 4; ++c) {
        float4 nr, nz, nn4;
        if (c < 2) {
            int k2 = (c + 2) * 128 + lane * 4;
            nr = *(const float4*)(wr + k2);
            nz = *(const float4*)(wz + k2);
            nn4 = *(const float4*)(wn + k2);
        }
        int kc = c * 128 + lane * 4;
#pragma unroll
        for (int n = 0; n < NN; ++n) {
            float4 h4 = *(const float4*)(shh + n * 1024 + kc);
            ar[n] += c0r.x * h4.x + c0r.y * h4.y + c0r.z * h4.z + c0r.w * h4.w;
            az[n] += c0z.x * h4.x + c0z.y * h4.y + c0z.z * h4.z + c0z.w * h4.w;
            an[n] += c0n.x * h4.x + c0n.y * h4.y + c0n.z * h4.z + c0n.w * h4.w;
        }
        c0r = c1r; c0z = c1z; c0n = c1n;
        c1r = nr;  c1z = nz;  c1n = nn4;
    }

#pragma unroll
    for (int n = 0; n < NN; ++n) {
#pragma unroll
        for (int off = 16; off; off >>= 1) {
            ar[n] += __shfl_xor_sync(0xFFFFFFFFu, ar[n], off);
            az[n] += __shfl_xor_sync(0xFFFFFFFFu, az[n], off);
            an[n] += __shfl_xor_sync(0xFFFFFFFFu, an[n], off);
        }
    }
#pragma unroll
    for (int n = 0; n < NN; ++n) {
        if (lane == n) {
            smP[(wid * 3 + 0) * NN + n] = ar[n];
            smP[(wid * 3 + 1) * NN + n] = az[n];
            smP[(wid * 3 + 2) * NN + n] = an[n];
        }
    }
    __syncthreads();

    if (khalf == 0 && lane < NN) {
        int n = lane;
        float dr = smP[(wid * 3 + 0) * NN + n] + smP[((wid + 1) * 3 + 0) * NN + n];
        float dz = smP[(wid * 3 + 1) * NN + n] + smP[((wid + 1) * 3 + 1) * NN + n];
        float dn = smP[(wid * 3 + 2) * NN + n] + smP[((wid + 1) * 3 + 2) * NN + n];
        const float* bih = side ? bih_r : bih_l;
        const float* bhh = side ? bhh_r : bhh_l;
        float r = fast_sigmoid(bih[j] + bhh[j] + dr);
        float z = fast_sigmoid(bih[1024 + j] + bhh[1024 + j] + dz);
        float nn_ = fast_tanh(bih[2048 + j] + r * (dn + bhh[2048 + j]));
        float h = sh[n * 1024 + j];
        float ho = (1.f - z) * nn_ + z * h;
        int orow = n * 2 + side;
        h_out[(size_t)orow * 1024 + j] = ho;
        hi_out[(size_t)orow * 1024 + j] = __float2bfloat16(ho);
    }
}

// ============================ tree MMA + fused gate (single-product bf16, d3-d9) ============================
// smem: A 2x16K @0, B 2x12K @32768  (56KB), occ 2.
__global__ __launch_bounds__(256, 2)
void tree_mma_fused(const __nv_bfloat16* __restrict__ a_hi,
                    const float* __restrict__ h_in,
                    const __nv_bfloat16* __restrict__ w_hi,
                    const float* __restrict__ bih_l, const float* __restrict__ bhh_l,
                    const float* __restrict__ bih_r, const float* __restrict__ bhh_r,
                    float* __restrict__ h_out, __nv_bfloat16* __restrict__ hi_out,
                    int Nn) {
    extern __shared__ char smem_raw[];
    const uint32_t sb = smem_to_u32(smem_raw);
    const int tid = threadIdx.x;
    const int wid = tid >> 5, lane = tid & 31;
    const int warp_m = wid & 3, warp_n = wid >> 2;
    const int m0 = blockIdx.x * 128;
    const int jb = blockIdx.y;
    const int side = blockIdx.z;

    float acc[2][6][4];
#pragma unroll
    for (int mi = 0; mi < 2; ++mi)
#pragma unroll
        for (int nj = 0; nj < 6; ++nj)
#pragma unroll
            for (int c = 0; c < 4; ++c) acc[mi][nj][c] = 0.f;

    auto load_tile = [&](int t, int buf) {
        const int k0 = t * 64;
        const uint32_t ahbase = sb + buf * 16384;
        const uint32_t bhbase = sb + 32768 + buf * 12288;
#pragma unroll
        for (int i = 0; i < 4; ++i) {
            int idx = tid + i * 256;
            int row = idx >> 3, ch = idx & 7;
            int arow = m0 + row; if (arow >= Nn) arow = Nn - 1;
            size_t goff = (size_t)arow * H + k0 + ch * 8;
            cp_async_16(ahbase + SMEM_SWIZZLE_128B(row * 128 + ch * 16), a_hi + goff);
        }
#pragma unroll
        for (int i = 0; i < 3; ++i) {
            int idx = tid + i * 256;
            int row = idx >> 3, ch = idx & 7;
            int grow = side * 3072 + (row >> 5) * 1024 + jb * 32 + (row & 31);
            size_t goff = (size_t)grow * H + k0 + ch * 8;
            cp_async_16(bhbase + SMEM_SWIZZLE_128B(row * 128 + ch * 16), w_hi + goff);
        }
        cp_async_commit();
    };

    load_tile(0, 0);

    for (int t = 0; t < 16; ++t) {
        if (t < 15) { load_tile(t + 1, (t + 1) & 1); cp_async_wait<1>(); }
        else        { cp_async_wait<0>(); }
        __syncthreads();

        const int buf = t & 1;
        const uint32_t ahbase = sb + buf * 16384;
        const uint32_t bhbase = sb + 32768 + buf * 12288;

#pragma unroll
        for (int ks = 0; ks < 4; ++ks) {
            uint32_t ah[2][4];
#pragma unroll
            for (int mi = 0; mi < 2; ++mi) {
                int row = warp_m * 32 + mi * 16 + (lane & 15);
                int byte = ks * 32 + ((lane >> 4) << 4);
                ldmatrix_x4(ah[mi][0], ah[mi][1], ah[mi][2], ah[mi][3],
                            ahbase + SMEM_SWIZZLE_128B(row * 128 + byte));
            }
            uint32_t bh[6][2];
#pragma unroll
            for (int p = 0; p < 3; ++p) {
                int nrow = warp_n * 48 + p * 16 + (lane & 7) + ((lane & 16) >> 1);
                int byte = ks * 32 + ((lane & 8) << 1);
                uint32_t r0, r1, r2, r3;
                ldmatrix_x4(r0, r1, r2, r3, bhbase + SMEM_SWIZZLE_128B(nrow * 128 + byte));
                bh[p * 2][0] = r0; bh[p * 2][1] = r1; bh[p * 2 + 1][0] = r2; bh[p * 2 + 1][1] = r3;
            }
#pragma unroll
            for (int mi = 0; mi < 2; ++mi)
#pragma unroll
                for (int nj = 0; nj < 6; ++nj)
                    mma_bf16(acc[mi][nj], ah[mi], bh[nj]);
        }
        __syncthreads();
    }

    // ---- epilogue: acc -> smem -> gate ----
    float* sG = (float*)smem_raw;   // [128][100]
#pragma unroll
    for (int mi = 0; mi < 2; ++mi)
#pragma unroll
        for (int hh = 0; hh < 2; ++hh) {
            int row = warp_m * 32 + mi * 16 + hh * 8 + (lane >> 2);
#pragma unroll
            for (int nj = 0; nj < 6; ++nj) {
                int c = warp_n * 48 + nj * 8 + (lane & 3) * 2;
                sG[row * 100 + c]     = acc[mi][nj][hh * 2];
                sG[row * 100 + c + 1] = acc[mi][nj][hh * 2 + 1];
            }
        }
    __syncthreads();

    const float* bih = side ? bih_r : bih_l;
    const float* bhh = side ? bhh_r : bhh_l;
#pragma unroll
    for (int it = 0; it < 16; ++it) {
        int e = tid + it * 256;
        int m = e >> 5, i = e & 31;
        int node = m0 + m;
        if (node < Nn) {
            int j = jb * 32 + i;
            float dr = sG[m * 100 + i];
            float dz = sG[m * 100 + 32 + i];
            float dn = sG[m * 100 + 64 + i];
            float h = h_in[(size_t)node * 1024 + j];
            float r = fast_sigmoid(bih[j] + bhh[j] + dr);
            float z = fast_sigmoid(bih[1024 + j] + bhh[1024 + j] + dz);
            float nn_ = fast_tanh(bih[2048 + j] + r * (dn + bhh[2048 + j]));
            float ho = (1.f - z) * nn_ + z * h;
            size_t orow = (size_t)(node * 2 + side) * 1024 + j;
            h_out[orow] = ho;
            hi_out[orow] = __float2bfloat16(ho);
        }
    }
}

// ============================ final logits GEMM (dual bf16, 3-stage, occ 2, fp16 out) ============================
__global__ __launch_bounds__(256, 2)
void logits_gemm_kernel(const __nv_bfloat16* __restrict__ A,
                        const __nv_bfloat16* __restrict__ B,
                        const float* __restrict__ bout,
                        __half* __restrict__ gl,
                        float* __restrict__ pmax, float* __restrict__ psum) {
    extern __shared__ char smem_raw[];
    const uint32_t sb = smem_to_u32(smem_raw);
    const int tid = threadIdx.x;
    const int wid = tid >> 5, lane = tid & 31;
    const int warp_m = wid & 3, warp_n = wid >> 2;
    const int m0 = blockIdx.x * 128;
    const int n0 = blockIdx.y * 128;

    float acc[2][8][4];
#pragma unroll
    for (int mi = 0; mi < 2; ++mi)
#pragma unroll
        for (int ni = 0; ni < 8; ++ni)
#pragma unroll
            for (int c = 0; c < 4; ++c) acc[mi][ni][c] = 0.f;

    auto load_tile = [&](int t, int buf) {
        const int k0 = t * 64;
        const uint32_t abase = sb + buf * 16384;
        const uint32_t bbase = sb + 49152 + buf * 16384;
#pragma unroll
        for (int i = 0; i < 4; ++i) {
            int idx = tid + i * 256;
            int row = idx >> 3, ch = idx & 7;
            cp_async_16(abase + SMEM_SWIZZLE_128B(row * 128 + ch * 16),
                        A + (size_t)(m0 + row) * H + k0 + ch * 8);
        }
#pragma unroll
        for (int i = 0; i < 4; ++i) {
            int idx = tid + i * 256;
            int row = idx >> 3, ch = idx & 7;
            cp_async_16(bbase + SMEM_SWIZZLE_128B(row * 128 + ch * 16),
                        B + (size_t)(n0 + row) * H + k0 + ch * 8);
        }
        cp_async_commit();
    };

    load_tile(0, 0);
    load_tile(1, 1);

    for (int t = 0; t < 16; ++t) {
        if (t < 14)       { load_tile(t + 2, (t + 2) % 3); cp_async_wait<2>(); }
        else if (t == 14) { cp_async_wait<1>(); }
        else              { cp_async_wait<0>(); }
        __syncthreads();

        const int buf = t % 3;
        const uint32_t abase = sb + buf * 16384;
        const uint32_t bbase = sb + 49152 + buf * 16384;

#pragma unroll
        for (int ks = 0; ks < 4; ++ks) {
            uint32_t a[2][4];
#pragma unroll
            for (int mi = 0; mi < 2; ++mi) {
                int row = warp_m * 32 + mi * 16 + (lane & 15);
                int byte = ks * 32 + ((lane >> 4) << 4);
                ldmatrix_x4(a[mi][0], a[mi][1], a[mi][2], a[mi][3],
                            abase + SMEM_SWIZZLE_128B(row * 128 + byte));
            }
            uint32_t bb[8][2];
#pragma unroll
            for (int nj = 0; nj < 4; ++nj) {
                int nrow = warp_n * 64 + nj * 16 + (lane & 7) + ((lane & 16) >> 1);
                int byte = ks * 32 + ((lane & 8) << 1);
                uint32_t r0, r1, r2, r3;
                ldmatrix_x4(r0, r1, r2, r3,
                            bbase + SMEM_SWIZZLE_128B(nrow * 128 + byte));
                bb[nj * 2][0] = r0;     bb[nj * 2][1] = r1;
                bb[nj * 2 + 1][0] = r2; bb[nj * 2 + 1][1] = r3;
            }
#pragma unroll
            for (int mi = 0; mi < 2; ++mi)
#pragma unroll
                for (int ni = 0; ni < 8; ++ni)
                    mma_bf16(acc[mi][ni], a[mi], bb[ni]);
        }
        __syncthreads();
    }

    // ---- epilogue ----
    float* sMax = (float*)smem_raw;
    float* sSum = (float*)(smem_raw + 1024);

    float2 bias[8];
#pragma unroll
    for (int ni = 0; ni < 8; ++ni)
        bias[ni] = *(const float2*)(bout + n0 + warp_n * 64 + ni * 8 + (lane & 3) * 2);

#pragma unroll
    for (int mi = 0; mi < 2; ++mi) {
#pragma unroll
        for (int hi = 0; hi < 2; ++hi) {
            int row_l = warp_m * 32 + mi * 16 + hi * 8 + (lane >> 2);
            int grow = m0 + row_l;
            float v[16];
            float rmax = -1e30f;
#pragma unroll
            for (int ni = 0; ni < 8; ++ni) {
                v[2 * ni]     = acc[mi][ni][hi * 2]     + bias[ni].x;
                v[2 * ni + 1] = acc[mi][ni][hi * 2 + 1] + bias[ni].y;
                rmax = fmaxf(rmax, fmaxf(v[2 * ni], v[2 * ni + 1]));
            }
            rmax = fmaxf(rmax, __shfl_xor_sync(0xFFFFFFFFu, rmax, 1));
            rmax = fmaxf(rmax, __shfl_xor_sync(0xFFFFFFFFu, rmax, 2));
            float rsum = 0.f;
#pragma unroll
            for (int i = 0; i < 16; ++i) rsum += __expf(v[i] - rmax);
            rsum += __shfl_xor_sync(0xFFFFFFFFu, rsum, 1);
            rsum += __shfl_xor_sync(0xFFFFFFFFu, rsum, 2);

            __half* op = gl + (size_t)grow * VOCAB + n0 + warp_n * 64 + (lane & 3) * 2;
#pragma unroll
            for (int ni = 0; ni < 8; ++ni) {
                __half2 hv = __floats2half2_rn(v[2 * ni], v[2 * ni + 1]);
                __stcs((unsigned int*)(op + ni * 8), *(unsigned int*)&hv);
            }

            if ((lane & 3) == 0) {
                sMax[row_l * 2 + warp_n] = rmax;
                sSum[row_l * 2 + warp_n] = rsum;
            }
        }
    }
    __syncthreads();
    if (tid < 128) {
        float ma = sMax[tid * 2], mb = sMax[tid * 2 + 1];
        float g = fmaxf(ma, mb);
        float s = sSum[tid * 2] * __expf(ma - g) + sSum[tid * 2 + 1] * __expf(mb - g);
        pmax[(size_t)(m0 + tid) * NTILES + blockIdx.y] = g;
        psum[(size_t)(m0 + tid) * NTILES + blockIdx.y] = s;
    }
}

// ============================ LSE combine + final subtract ============================
__global__ void lse_reduce_kernel(const float* __restrict__ pmax, const float* __restrict__ psum,
                                  float* __restrict__ lse) {
    __shared__ float sm[256];
    __shared__ float ss[256];
    const int r = blockIdx.x, t = threadIdx.x;
    float m = (t < NTILES) ? pmax[(size_t)r * NTILES + t] : -1e30f;
    sm[t] = m;
    __syncthreads();
    for (int s = 128; s > 0; s >>= 1) {
        if (t < s) sm[t] = fmaxf(sm[t], sm[t + s]);
        __syncthreads();
    }
    float gmax = sm[0];
    float sv = (t < NTILES) ? psum[(size_t)r * NTILES + t] * __expf(pmax[(size_t)r * NTILES + t] - gmax) : 0.f;
    ss[t] = sv;
    __syncthreads();
    for (int s = 128; s > 0; s >>= 1) {
        if (t < s) ss[t] += ss[t + s];
        __syncthreads();
    }
    if (t == 0) lse[r] = gmax + logf(ss[0]);
}

__global__ void sub_lse_kernel(const __half* __restrict__ gl, float* __restrict__ out,
                               const float* __restrict__ lse) {
    int i = blockIdx.x * blockDim.x + threadIdx.x;
    if (i < H * (VOCAB / 8)) {
        uint4 raw = __ldcs((const uint4*)gl + i);
        float l = __ldg(&lse[i / (VOCAB / 8)]);
        __half2* hp = (__half2*)&raw;
        float2 f0 = __half22float2(hp[0]);
        float2 f1 = __half22float2(hp[1]);
        float2 f2 = __half22float2(hp[2]);
        float2 f3 = __half22float2(hp[3]);
        float4 o0 = make_float4(f0.x - l, f0.y - l, f1.x - l, f1.y - l);
        float4 o1 = make_float4(f2.x - l, f2.y - l, f3.x - l, f3.y - l);
        __stcs((float4*)out + i * 2,     o0);
        __stcs((float4*)out + i * 2 + 1, o1);
    }
}

// ============================ launch ============================
extern "C" void kernel_launch(void* const* d_in, const int* in_sizes, int n_in,
                              void* d_out, int out_size) {
    const float* hidden = (const float*)d_in[0];
    const float* Whh_l  = (const float*)d_in[1];
    const float* bih_l  = (const float*)d_in[2];
    const float* bhh_l  = (const float*)d_in[3];
    const float* Whh_r  = (const float*)d_in[4];
    const float* bih_r  = (const float*)d_in[5];
    const float* bhh_r  = (const float*)d_in[6];
    const float* Wout   = (const float*)d_in[7];
    const float* bout   = (const float*)d_in[8];
    (void)in_sizes; (void)n_in; (void)out_size;

    float *hbuf[2], *pmax, *psum, *lse;
    __nv_bfloat16 *hhi[2], *whi, *wb;
    __half* gl;
    cudaGetSymbolAddress((void**)&hbuf[0], g_hbuf0);
    cudaGetSymbolAddress((void**)&hbuf[1], g_hbuf1);
    cudaGetSymbolAddress((void**)&hhi[0],  g_hhi0);
    cudaGetSymbolAddress((void**)&hhi[1],  g_hhi1);
    cudaGetSymbolAddress((void**)&whi,     g_whi);
    cudaGetSymbolAddress((void**)&wb,      g_w_bf16);
    cudaGetSymbolAddress((void**)&gl,      g_logits);
    cudaGetSymbolAddress((void**)&pmax,    g_pmax);
    cudaGetSymbolAddress((void**)&psum,    g_psum);
    cudaGetSymbolAddress((void**)&lse,     g_lse);

    cudaFuncSetAttribute(logits_gemm_kernel, cudaFuncAttributeMaxDynamicSharedMemorySize, 98304);
    cudaFuncSetAttribute(tree_mma_fused,     cudaFuncAttributeMaxDynamicSharedMemorySize, 57344);

    // side stream objects (created once)
    static cudaStream_t s2 = nullptr;
    static cudaEvent_t evFork = nullptr, evJoin = nullptr;
    if (!s2) {
        cudaStreamCreateWithFlags(&s2, cudaStreamNonBlocking);
        cudaEventCreateWithFlags(&evFork, cudaEventDisableTiming);
        cudaEventCreateWithFlags(&evJoin, cudaEventDisableTiming);
    }

    // depths 0-2: fp32 GEMV + background Whh->bf16 conversion
    for (int d = 0; d <= 2; ++d) {
        const float* in = (d == 0) ? hidden : hbuf[d & 1];
        int o = (d + 1) & 1;
        int NN = 1 << d;
        size_t shmem = (size_t)NN * 1024 * sizeof(float) + 8 * 3 * NN * sizeof(float);
        int conv_base4 = d * 524288;
        switch (d) {
        case 0: gemv_split_kernel<1><<<1024, 256, shmem>>>(in, Whh_l, bih_l, bhh_l, Whh_r, bih_r, bhh_r,
                 hbuf[o], hhi[o], whi, conv_base4); break;
        case 1: gemv_split_kernel<2><<<1024, 256, shmem>>>(in, Whh_l, bih_l, bhh_l, Whh_r, bih_r, bhh_r,
                 hbuf[o], hhi[o], whi, conv_base4); break;
        default: gemv_split_kernel<4><<<1024, 256, shmem>>>(in, Whh_l, bih_l, bhh_l, Whh_r, bih_r, bhh_r,
                 hbuf[o], hhi[o], whi, conv_base4); break;
        }
    }

    // depths 3-4: bf16 MMA (whi fully written after d2 by stream order; conv stream not yet running,
    // so whi stays L2-warm for these latency-sensitive 64-CTA launches)
    for (int d = 3; d <= 4; ++d) {
        int Nn = 1 << d;
        int ii = d & 1, o = (d + 1) & 1;
        dim3 mg(1, 32, 2);
        tree_mma_fused<<<mg, 256, 57344>>>(hhi[ii], hbuf[ii], whi,
                                           bih_l, bhh_l, bih_r, bhh_r,
                                           hbuf[o], hhi[o], Nn);
    }

    // fork: Wout fp32->bf16 overlaps depths 5-9
    cudaEventRecord(evFork, 0);
    cudaStreamWaitEvent(s2, evFork, 0);
    wout_conv_kernel<<<2048, 256, 0, s2>>>(Wout, wb);
    cudaEventRecord(evJoin, s2);

    // depths 5-9: single-product bf16 MMA with fused gating
    for (int d = 5; d <= 9; ++d) {
        int Nn = 1 << d;
        int ii = d & 1, o = (d + 1) & 1;
        dim3 mg((Nn + 127) / 128, 32, 2);
        tree_mma_fused<<<mg, 256, 57344>>>(hhi[ii], hbuf[ii], whi,
                                           bih_l, bhh_l, bih_r, bhh_r,
                                           hbuf[o], hhi[o], Nn);
    }

    // join conversion stream, then logits (fp16 scratch out)
    cudaStreamWaitEvent(0, evJoin, 0);
    dim3 ggrid(8, NTILES);
    logits_gemm_kernel<<<ggrid, 256, 98304>>>(hhi[0], wb, bout, gl, pmax, psum);

    lse_reduce_kernel<<<H, 256>>>(pmax, psum, lse);
    sub_lse_kernel<<<(H * (VOCAB / 8) + 255) / 256, 256>>>(gl, (float*)d_out, lse);
}

// round 15
// speedup vs baseline: 1.0409x; 1.0409x over previous
#include <cuda_runtime.h>
#include <cuda_bf16.h>
#include <cuda_fp16.h>
#include <cstdint>
#include <math.h>

#define H 1024
#define VOCAB 32000
#define NTILES 250   // 32000/128

// ============================ helpers ============================
__device__ __forceinline__ uint32_t smem_to_u32(const void* smem_ptr) {
    uint32_t addr;
    asm("{ .reg .u64 tmp; cvta.to.shared.u64 tmp, %1; cvt.u32.u64 %0, tmp; }"
        : "=r"(addr) : "l"(smem_ptr));
    return addr;
}

#define SMEM_SWIZZLE_128B(byte_offset) \
    ((byte_offset) ^ (((byte_offset) >> 3) & 0x70))

__device__ __forceinline__ void cp_async_16(uint32_t smem_addr, const void* gmem) {
    asm volatile("cp.async.cg.shared.global [%0], [%1], 16;" :: "r"(smem_addr), "l"(gmem));
}
__device__ __forceinline__ void cp_async_commit() {
    asm volatile("cp.async.commit_group;" ::: "memory");
}
template <int N>
__device__ __forceinline__ void cp_async_wait() {
    asm volatile("cp.async.wait_group %0;" :: "n"(N) : "memory");
}

__device__ __forceinline__ void ldmatrix_x4(uint32_t& r0, uint32_t& r1, uint32_t& r2, uint32_t& r3,
                                            uint32_t addr) {
    asm volatile("ldmatrix.sync.aligned.m8n8.x4.shared.b16 {%0,%1,%2,%3}, [%4];"
                 : "=r"(r0), "=r"(r1), "=r"(r2), "=r"(r3) : "r"(addr));
}

__device__ __forceinline__ void mma_bf16(float* d, const uint32_t* a, const uint32_t* b) {
    asm volatile(
        "mma.sync.aligned.m16n8k16.row.col.f32.bf16.bf16.f32 "
        "{%0,%1,%2,%3}, {%4,%5,%6,%7}, {%8,%9}, {%0,%1,%2,%3};"
        : "+f"(d[0]), "+f"(d[1]), "+f"(d[2]), "+f"(d[3])
        : "r"(a[0]), "r"(a[1]), "r"(a[2]), "r"(a[3]), "r"(b[0]), "r"(b[1]));
}

__device__ __forceinline__ float fast_sigmoid(float x) {
    return __fdividef(1.f, 1.f + __expf(-x));
}
__device__ __forceinline__ float fast_tanh(float x) {
    float xc = fminf(fmaxf(x, -15.f), 15.f);
    float t = __expf(2.f * xc);
    return __fdividef(t - 1.f, t + 1.f);
}

__device__ __forceinline__ void bf16x8_to_f32(const uint4& u, float* f) {
    f[0] = __uint_as_float(u.x << 16); f[1] = __uint_as_float(u.x & 0xFFFF0000u);
    f[2] = __uint_as_float(u.y << 16); f[3] = __uint_as_float(u.y & 0xFFFF0000u);
    f[4] = __uint_as_float(u.z << 16); f[5] = __uint_as_float(u.z & 0xFFFF0000u);
    f[6] = __uint_as_float(u.w << 16); f[7] = __uint_as_float(u.w & 0xFFFF0000u);
}

// ============================ device scratch ============================
__device__ __align__(16) float          g_hbuf0[H * H];
__device__ __align__(16) float          g_hbuf1[H * H];
__device__ __align__(16) __nv_bfloat16  g_hhi0[H * H];
__device__ __align__(16) __nv_bfloat16  g_hhi1[H * H];
__device__ __align__(16) __nv_bfloat16  g_whi[6144 * H];
__device__ __align__(16) __nv_bfloat16  g_w_bf16[(size_t)VOCAB * H];
__device__ __align__(16) __half         g_logits[(size_t)H * VOCAB];
__device__ float g_pmax[H * NTILES];
__device__ float g_psum[H * NTILES];
__device__ float g_lse[H];

// ============================ Wout conversion (side stream) ============================
__global__ __launch_bounds__(256)
void wout_conv_kernel(const float* __restrict__ W, __nv_bfloat16* __restrict__ wb) {
    for (int i4 = blockIdx.x * 256 + threadIdx.x; i4 < 8192000; i4 += gridDim.x * 256) {
        float4 v = __ldcs((const float4*)W + i4);
        __nv_bfloat162 h2[2];
        h2[0] = __floats2bfloat162_rn(v.x, v.y);
        h2[1] = __floats2bfloat162_rn(v.z, v.w);
        uint32_t u0 = *(uint32_t*)&h2[0];
        uint32_t u1 = *(uint32_t*)&h2[1];
        __stcs((uint32_t*)(wb + i4 * 4),     u0);
        __stcs((uint32_t*)(wb + i4 * 4 + 2), u1);
    }
}

// ============================ Whh -> bf16 conversion chunk (background in d0-d2) ============================
__device__ __forceinline__ void wsplit_chunk(const float* __restrict__ Wl, const float* __restrict__ Wr,
                                             __nv_bfloat16* __restrict__ whi,
                                             int conv_base4, int cbid, int tid) {
#pragma unroll
    for (int u = 0; u < 4; ++u) {
        int i4 = conv_base4 + cbid * 1024 + u * 256 + tid;
        int i = i4 * 4;
        const float* src = (i < 3072 * H) ? Wl : Wr;
        int off = (i < 3072 * H) ? i : i - 3072 * H;
        float4 v = *(const float4*)(src + off);
        __nv_bfloat162 hi2[2];
        hi2[0] = __floats2bfloat162_rn(v.x, v.y);
        hi2[1] = __floats2bfloat162_rn(v.z, v.w);
        *(uint32_t*)(whi + i)     = *(uint32_t*)&hi2[0];
        *(uint32_t*)(whi + i + 2) = *(uint32_t*)&hi2[1];
    }
}

// ============================ K-split GEMV, fp32 W (d0-d2) ============================
template <int NN>
__global__ __launch_bounds__(256)
void gemv_split_kernel(const float* __restrict__ h_in,
                       const float* __restrict__ Whh_l, const float* __restrict__ bih_l,
                       const float* __restrict__ bhh_l,
                       const float* __restrict__ Whh_r, const float* __restrict__ bih_r,
                       const float* __restrict__ bhh_r,
                       float* __restrict__ h_out, __nv_bfloat16* __restrict__ hi_out,
                       __nv_bfloat16* __restrict__ whi,
                       int conv_base4) {
    const int tid = threadIdx.x;
    if (blockIdx.x >= 512) {
        wsplit_chunk(Whh_l, Whh_r, whi, conv_base4, blockIdx.x - 512, tid);
        return;
    }

    extern __shared__ float sh[];
    float* smP = sh + NN * 1024;

    const int wid = tid >> 5, lane = tid & 31;
    const int pair = blockIdx.x * 4 + (wid >> 1);
    const int khalf = wid & 1;
    const int side = pair >> 10;
    const int j = pair & 1023;
    const float* __restrict__ W = side ? Whh_r : Whh_l;
    const float* wr = W + (size_t)j * 1024 + khalf * 512;
    const float* wz = W + (size_t)(1024 + j) * 1024 + khalf * 512;
    const float* wn = W + (size_t)(2048 + j) * 1024 + khalf * 512;
    const float* shh = sh + khalf * 512;

    // W prefetch (in flight during h staging)
    float4 c0r = *(const float4*)(wr + lane * 4);
    float4 c0z = *(const float4*)(wz + lane * 4);
    float4 c0n = *(const float4*)(wn + lane * 4);
    float4 c1r = *(const float4*)(wr + 128 + lane * 4);
    float4 c1z = *(const float4*)(wz + 128 + lane * 4);
    float4 c1n = *(const float4*)(wn + 128 + lane * 4);

    for (int i = tid; i < NN * 1024; i += 256) sh[i] = h_in[i];
    __syncthreads();

    float ar[NN], az[NN], an[NN];
#pragma unroll
    for (int n = 0; n < NN; ++n) { ar[n] = 0.f; az[n] = 0.f; an[n] = 0.f; }

#pragma unroll 1
    for (int c = 0; c < 4; ++c) {
        float4 nr, nz, nn4;
        if (c < 2) {
            int k2 = (c + 2) * 128 + lane * 4;
            nr = *(const float4*)(wr + k2);
            nz = *(const float4*)(wz + k2);
            nn4 = *(const float4*)(wn + k2);
        }
        int kc = c * 128 + lane * 4;
#pragma unroll
        for (int n = 0; n < NN; ++n) {
            float4 h4 = *(const float4*)(shh + n * 1024 + kc);
            ar[n] += c0r.x * h4.x + c0r.y * h4.y + c0r.z * h4.z + c0r.w * h4.w;
            az[n] += c0z.x * h4.x + c0z.y * h4.y + c0z.z * h4.z + c0z.w * h4.w;
            an[n] += c0n.x * h4.x + c0n.y * h4.y + c0n.z * h4.z + c0n.w * h4.w;
        }
        c0r = c1r; c0z = c1z; c0n = c1n;
        c1r = nr;  c1z = nz;  c1n = nn4;
    }

#pragma unroll
    for (int n = 0; n < NN; ++n) {
#pragma unroll
        for (int off = 16; off; off >>= 1) {
            ar[n] += __shfl_xor_sync(0xFFFFFFFFu, ar[n], off);
            az[n] += __shfl_xor_sync(0xFFFFFFFFu, az[n], off);
            an[n] += __shfl_xor_sync(0xFFFFFFFFu, an[n], off);
        }
    }
#pragma unroll
    for (int n = 0; n < NN; ++n) {
        if (lane == n) {
            smP[(wid * 3 + 0) * NN + n] = ar[n];
            smP[(wid * 3 + 1) * NN + n] = az[n];
            smP[(wid * 3 + 2) * NN + n] = an[n];
        }
    }
    __syncthreads();

    if (khalf == 0 && lane < NN) {
        int n = lane;
        float dr = smP[(wid * 3 + 0) * NN + n] + smP[((wid + 1) * 3 + 0) * NN + n];
        float dz = smP[(wid * 3 + 1) * NN + n] + smP[((wid + 1) * 3 + 1) * NN + n];
        float dn = smP[(wid * 3 + 2) * NN + n] + smP[((wid + 1) * 3 + 2) * NN + n];
        const float* bih = side ? bih_r : bih_l;
        const float* bhh = side ? bhh_r : bhh_l;
        float r = fast_sigmoid(bih[j] + bhh[j] + dr);
        float z = fast_sigmoid(bih[1024 + j] + bhh[1024 + j] + dz);
        float nn_ = fast_tanh(bih[2048 + j] + r * (dn + bhh[2048 + j]));
        float h = sh[n * 1024 + j];
        float ho = (1.f - z) * nn_ + z * h;
        int orow = n * 2 + side;
        h_out[(size_t)orow * 1024 + j] = ho;
        hi_out[(size_t)orow * 1024 + j] = __float2bfloat16(ho);
    }
}

// ============================ K-split GEMV, bf16 W (d3-d4) ============================
template <int NN>
__global__ __launch_bounds__(256)
void gemv_split_bf16(const float* __restrict__ h_in,
                     const __nv_bfloat16* __restrict__ whi,
                     const float* __restrict__ bih_l, const float* __restrict__ bhh_l,
                     const float* __restrict__ bih_r, const float* __restrict__ bhh_r,
                     float* __restrict__ h_out, __nv_bfloat16* __restrict__ hi_out) {
    extern __shared__ float sh[];
    float* smP = sh + NN * 1024;
    const int tid = threadIdx.x;

    const int wid = tid >> 5, lane = tid & 31;
    const int pair = blockIdx.x * 4 + (wid >> 1);
    const int khalf = wid & 1;
    const int side = pair >> 10;
    const int j = pair & 1023;
    const __nv_bfloat16* wr = whi + (size_t)(side * 3072 + j) * 1024 + khalf * 512;
    const __nv_bfloat16* wz = whi + (size_t)(side * 3072 + 1024 + j) * 1024 + khalf * 512;
    const __nv_bfloat16* wn = whi + (size_t)(side * 3072 + 2048 + j) * 1024 + khalf * 512;
    const float* shh = sh + khalf * 512;

    // all 6 W uint4 in flight before staging
    uint4 w0r = *(const uint4*)(wr + lane * 8);
    uint4 w0z = *(const uint4*)(wz + lane * 8);
    uint4 w0n = *(const uint4*)(wn + lane * 8);
    uint4 w1r = *(const uint4*)(wr + 256 + lane * 8);
    uint4 w1z = *(const uint4*)(wz + 256 + lane * 8);
    uint4 w1n = *(const uint4*)(wn + 256 + lane * 8);

    for (int i = tid; i < NN * 1024; i += 256) sh[i] = h_in[i];
    __syncthreads();

    float ar[NN], az[NN], an[NN];
#pragma unroll
    for (int n = 0; n < NN; ++n) { ar[n] = 0.f; az[n] = 0.f; an[n] = 0.f; }

#pragma unroll
    for (int c = 0; c < 2; ++c) {
        float wrf[8], wzf[8], wnf[8];
        bf16x8_to_f32(c ? w1r : w0r, wrf);
        bf16x8_to_f32(c ? w1z : w0z, wzf);
        bf16x8_to_f32(c ? w1n : w0n, wnf);
        int kc = c * 256 + lane * 8;
#pragma unroll
        for (int n = 0; n < NN; ++n) {
            float4 ha = *(const float4*)(shh + n * 1024 + kc);
            float4 hb = *(const float4*)(shh + n * 1024 + kc + 4);
            ar[n] += wrf[0] * ha.x + wrf[1] * ha.y + wrf[2] * ha.z + wrf[3] * ha.w
                   + wrf[4] * hb.x + wrf[5] * hb.y + wrf[6] * hb.z + wrf[7] * hb.w;
            az[n] += wzf[0] * ha.x + wzf[1] * ha.y + wzf[2] * ha.z + wzf[3] * ha.w
                   + wzf[4] * hb.x + wzf[5] * hb.y + wzf[6] * hb.z + wzf[7] * hb.w;
            an[n] += wnf[0] * ha.x + wnf[1] * ha.y + wnf[2] * ha.z + wnf[3] * ha.w
                   + wnf[4] * hb.x + wnf[5] * hb.y + wnf[6] * hb.z + wnf[7] * hb.w;
        }
    }

#pragma unroll
    for (int n = 0; n < NN; ++n) {
#pragma unroll
        for (int off = 16; off; off >>= 1) {
            ar[n] += __shfl_xor_sync(0xFFFFFFFFu, ar[n], off);
            az[n] += __shfl_xor_sync(0xFFFFFFFFu, az[n], off);
            an[n] += __shfl_xor_sync(0xFFFFFFFFu, an[n], off);
        }
    }
#pragma unroll
    for (int n = 0; n < NN; ++n) {
        if (lane == (n & 31)) {
            smP[(wid * 3 + 0) * NN + n] = ar[n];
            smP[(wid * 3 + 1) * NN + n] = az[n];
            smP[(wid * 3 + 2) * NN + n] = an[n];
        }
    }
    __syncthreads();

    if (khalf == 0) {
#pragma unroll
        for (int n = lane; n < NN; n += 32) {
            float dr = smP[(wid * 3 + 0) * NN + n] + smP[((wid + 1) * 3 + 0) * NN + n];
            float dz = smP[(wid * 3 + 1) * NN + n] + smP[((wid + 1) * 3 + 1) * NN + n];
            float dn = smP[(wid * 3 + 2) * NN + n] + smP[((wid + 1) * 3 + 2) * NN + n];
            const float* bih = side ? bih_r : bih_l;
            const float* bhh = side ? bhh_r : bhh_l;
            float r = fast_sigmoid(bih[j] + bhh[j] + dr);
            float z = fast_sigmoid(bih[1024 + j] + bhh[1024 + j] + dz);
            float nn_ = fast_tanh(bih[2048 + j] + r * (dn + bhh[2048 + j]));
            float h = sh[n * 1024 + j];
            float ho = (1.f - z) * nn_ + z * h;
            int orow = n * 2 + side;
            h_out[(size_t)orow * 1024 + j] = ho;
            hi_out[(size_t)orow * 1024 + j] = __float2bfloat16(ho);
        }
    }
}

// ============================ tree MMA + fused gate (bf16, 3-stage pipeline, d5-d9) ============================
// smem: A 3x16K @0, B 3x12K @49152  (84KB), occ 2 (168 <= 227KB).
__global__ __launch_bounds__(256, 2)
void tree_mma_fused(const __nv_bfloat16* __restrict__ a_hi,
                    const float* __restrict__ h_in,
                    const __nv_bfloat16* __restrict__ w_hi,
                    const float* __restrict__ bih_l, const float* __restrict__ bhh_l,
                    const float* __restrict__ bih_r, const float* __restrict__ bhh_r,
                    float* __restrict__ h_out, __nv_bfloat16* __restrict__ hi_out,
                    int Nn) {
    extern __shared__ char smem_raw[];
    const uint32_t sb = smem_to_u32(smem_raw);
    const int tid = threadIdx.x;
    const int wid = tid >> 5, lane = tid & 31;
    const int warp_m = wid & 3, warp_n = wid >> 2;
    const int m0 = blockIdx.x * 128;
    const int jb = blockIdx.y;
    const int side = blockIdx.z;

    float acc[2][6][4];
#pragma unroll
    for (int mi = 0; mi < 2; ++mi)
#pragma unroll
        for (int nj = 0; nj < 6; ++nj)
#pragma unroll
            for (int c = 0; c < 4; ++c) acc[mi][nj][c] = 0.f;

    auto load_tile = [&](int t, int buf) {
        const int k0 = t * 64;
        const uint32_t ahbase = sb + buf * 16384;
        const uint32_t bhbase = sb + 49152 + buf * 12288;
#pragma unroll
        for (int i = 0; i < 4; ++i) {
            int idx = tid + i * 256;
            int row = idx >> 3, ch = idx & 7;
            int arow = m0 + row; if (arow >= Nn) arow = Nn - 1;
            size_t goff = (size_t)arow * H + k0 + ch * 8;
            cp_async_16(ahbase + SMEM_SWIZZLE_128B(row * 128 + ch * 16), a_hi + goff);
        }
#pragma unroll
        for (int i = 0; i < 3; ++i) {
            int idx = tid + i * 256;
            int row = idx >> 3, ch = idx & 7;
            int grow = side * 3072 + (row >> 5) * 1024 + jb * 32 + (row & 31);
            size_t goff = (size_t)grow * H + k0 + ch * 8;
            cp_async_16(bhbase + SMEM_SWIZZLE_128B(row * 128 + ch * 16), w_hi + goff);
        }
        cp_async_commit();
    };

    load_tile(0, 0);
    load_tile(1, 1);

    for (int t = 0; t < 16; ++t) {
        if (t < 14)       { load_tile(t + 2, (t + 2) % 3); cp_async_wait<2>(); }
        else if (t == 14) { cp_async_wait<1>(); }
        else              { cp_async_wait<0>(); }
        __syncthreads();

        const int buf = t % 3;
        const uint32_t ahbase = sb + buf * 16384;
        const uint32_t bhbase = sb + 49152 + buf * 12288;

#pragma unroll
        for (int ks = 0; ks < 4; ++ks) {
            uint32_t ah[2][4];
#pragma unroll
            for (int mi = 0; mi < 2; ++mi) {
                int row = warp_m * 32 + mi * 16 + (lane & 15);
                int byte = ks * 32 + ((lane >> 4) << 4);
                ldmatrix_x4(ah[mi][0], ah[mi][1], ah[mi][2], ah[mi][3],
                            ahbase + SMEM_SWIZZLE_128B(row * 128 + byte));
            }
            uint32_t bh[6][2];
#pragma unroll
            for (int p = 0; p < 3; ++p) {
                int nrow = warp_n * 48 + p * 16 + (lane & 7) + ((lane & 16) >> 1);
                int byte = ks * 32 + ((lane & 8) << 1);
                uint32_t r0, r1, r2, r3;
                ldmatrix_x4(r0, r1, r2, r3, bhbase + SMEM_SWIZZLE_128B(nrow * 128 + byte));
                bh[p * 2][0] = r0; bh[p * 2][1] = r1; bh[p * 2 + 1][0] = r2; bh[p * 2 + 1][1] = r3;
            }
#pragma unroll
            for (int mi = 0; mi < 2; ++mi)
#pragma unroll
                for (int nj = 0; nj < 6; ++nj)
                    mma_bf16(acc[mi][nj], ah[mi], bh[nj]);
        }
        __syncthreads();
    }

    // ---- epilogue: acc -> smem -> gate ----
    float* sG = (float*)smem_raw;   // [128][100] = 51200B <= 84KB
#pragma unroll
    for (int mi = 0; mi < 2; ++mi)
#pragma unroll
        for (int hh = 0; hh < 2; ++hh) {
            int row = warp_m * 32 + mi * 16 + hh * 8 + (lane >> 2);
#pragma unroll
            for (int nj = 0; nj < 6; ++nj) {
                int c = warp_n * 48 + nj * 8 + (lane & 3) * 2;
                sG[row * 100 + c]     = acc[mi][nj][hh * 2];
                sG[row * 100 + c + 1] = acc[mi][nj][hh * 2 + 1];
            }
        }
    __syncthreads();

    const float* bih = side ? bih_r : bih_l;
    const float* bhh = side ? bhh_r : bhh_l;
#pragma unroll
    for (int it = 0; it < 16; ++it) {
        int e = tid + it * 256;
        int m = e >> 5, i = e & 31;
        int node = m0 + m;
        if (node < Nn) {
            int j = jb * 32 + i;
            float dr = sG[m * 100 + i];
            float dz = sG[m * 100 + 32 + i];
            float dn = sG[m * 100 + 64 + i];
            float h = h_in[(size_t)node * 1024 + j];
            float r = fast_sigmoid(bih[j] + bhh[j] + dr);
            float z = fast_sigmoid(bih[1024 + j] + bhh[1024 + j] + dz);
            float nn_ = fast_tanh(bih[2048 + j] + r * (dn + bhh[2048 + j]));
            float ho = (1.f - z) * nn_ + z * h;
            size_t orow = (size_t)(node * 2 + side) * 1024 + j;
            h_out[orow] = ho;
            hi_out[orow] = __float2bfloat16(ho);
        }
    }
}

// ============================ final logits GEMM (dual bf16, 3-stage, occ 2, fp16 out) ============================
__global__ __launch_bounds__(256, 2)
void logits_gemm_kernel(const __nv_bfloat16* __restrict__ A,
                        const __nv_bfloat16* __restrict__ B,
                        const float* __restrict__ bout,
                        __half* __restrict__ gl,
                        float* __restrict__ pmax, float* __restrict__ psum) {
    extern __shared__ char smem_raw[];
    const uint32_t sb = smem_to_u32(smem_raw);
    const int tid = threadIdx.x;
    const int wid = tid >> 5, lane = tid & 31;
    const int warp_m = wid & 3, warp_n = wid >> 2;
    const int m0 = blockIdx.x * 128;
    const int n0 = blockIdx.y * 128;

    float acc[2][8][4];
#pragma unroll
    for (int mi = 0; mi < 2; ++mi)
#pragma unroll
        for (int ni = 0; ni < 8; ++ni)
#pragma unroll
            for (int c = 0; c < 4; ++c) acc[mi][ni][c] = 0.f;

    auto load_tile = [&](int t, int buf) {
        const int k0 = t * 64;
        const uint32_t abase = sb + buf * 16384;
        const uint32_t bbase = sb + 49152 + buf * 16384;
#pragma unroll
        for (int i = 0; i < 4; ++i) {
            int idx = tid + i * 256;
            int row = idx >> 3, ch = idx & 7;
            cp_async_16(abase + SMEM_SWIZZLE_128B(row * 128 + ch * 16),
                        A + (size_t)(m0 + row) * H + k0 + ch * 8);
        }
#pragma unroll
        for (int i = 0; i < 4; ++i) {
            int idx = tid + i * 256;
            int row = idx >> 3, ch = idx & 7;
            cp_async_16(bbase + SMEM_SWIZZLE_128B(row * 128 + ch * 16),
                        B + (size_t)(n0 + row) * H + k0 + ch * 8);
        }
        cp_async_commit();
    };

    load_tile(0, 0);
    load_tile(1, 1);

    for (int t = 0; t < 16; ++t) {
        if (t < 14)       { load_tile(t + 2, (t + 2) % 3); cp_async_wait<2>(); }
        else if (t == 14) { cp_async_wait<1>(); }
        else              { cp_async_wait<0>(); }
        __syncthreads();

        const int buf = t % 3;
        const uint32_t abase = sb + buf * 16384;
        const uint32_t bbase = sb + 49152 + buf * 16384;

#pragma unroll
        for (int ks = 0; ks < 4; ++ks) {
            uint32_t a[2][4];
#pragma unroll
            for (int mi = 0; mi < 2; ++mi) {
                int row = warp_m * 32 + mi * 16 + (lane & 15);
                int byte = ks * 32 + ((lane >> 4) << 4);
                ldmatrix_x4(a[mi][0], a[mi][1], a[mi][2], a[mi][3],
                            abase + SMEM_SWIZZLE_128B(row * 128 + byte));
            }
            uint32_t bb[8][2];
#pragma unroll
            for (int nj = 0; nj < 4; ++nj) {
                int nrow = warp_n * 64 + nj * 16 + (lane & 7) + ((lane & 16) >> 1);
                int byte = ks * 32 + ((lane & 8) << 1);
                uint32_t r0, r1, r2, r3;
                ldmatrix_x4(r0, r1, r2, r3,
                            bbase + SMEM_SWIZZLE_128B(nrow * 128 + byte));
                bb[nj * 2][0] = r0;     bb[nj * 2][1] = r1;
                bb[nj * 2 + 1][0] = r2; bb[nj * 2 + 1][1] = r3;
            }
#pragma unroll
            for (int mi = 0; mi < 2; ++mi)
#pragma unroll
                for (int ni = 0; ni < 8; ++ni)
                    mma_bf16(acc[mi][ni], a[mi], bb[ni]);
        }
        __syncthreads();
    }

    // ---- epilogue ----
    float* sMax = (float*)smem_raw;
    float* sSum = (float*)(smem_raw + 1024);

    float2 bias[8];
#pragma unroll
    for (int ni = 0; ni < 8; ++ni)
        bias[ni] = *(const float2*)(bout + n0 + warp_n * 64 + ni * 8 + (lane & 3) * 2);

#pragma unroll
    for (int mi = 0; mi < 2; ++mi) {
#pragma unroll
        for (int hi = 0; hi < 2; ++hi) {
            int row_l = warp_m * 32 + mi * 16 + hi * 8 + (lane >> 2);
            int grow = m0 + row_l;
            float v[16];
            float rmax = -1e30f;
#pragma unroll
            for (int ni = 0; ni < 8; ++ni) {
                v[2 * ni]     = acc[mi][ni][hi * 2]     + bias[ni].x;
                v[2 * ni + 1] = acc[mi][ni][hi * 2 + 1] + bias[ni].y;
                rmax = fmaxf(rmax, fmaxf(v[2 * ni], v[2 * ni + 1]));
            }
            rmax = fmaxf(rmax, __shfl_xor_sync(0xFFFFFFFFu, rmax, 1));
            rmax = fmaxf(rmax, __shfl_xor_sync(0xFFFFFFFFu, rmax, 2));
            float rsum = 0.f;
#pragma unroll
            for (int i = 0; i < 16; ++i) rsum += __expf(v[i] - rmax);
            rsum += __shfl_xor_sync(0xFFFFFFFFu, rsum, 1);
            rsum += __shfl_xor_sync(0xFFFFFFFFu, rsum, 2);

            __half* op = gl + (size_t)grow * VOCAB + n0 + warp_n * 64 + (lane & 3) * 2;
#pragma unroll
            for (int ni = 0; ni < 8; ++ni) {
                __half2 hv = __floats2half2_rn(v[2 * ni], v[2 * ni + 1]);
                __stcs((unsigned int*)(op + ni * 8), *(unsigned int*)&hv);
            }

            if ((lane & 3) == 0) {
                sMax[row_l * 2 + warp_n] = rmax;
                sSum[row_l * 2 + warp_n] = rsum;
            }
        }
    }
    __syncthreads();
    if (tid < 128) {
        float ma = sMax[tid * 2], mb = sMax[tid * 2 + 1];
        float g = fmaxf(ma, mb);
        float s = sSum[tid * 2] * __expf(ma - g) + sSum[tid * 2 + 1] * __expf(mb - g);
        pmax[(size_t)(m0 + tid) * NTILES + blockIdx.y] = g;
        psum[(size_t)(m0 + tid) * NTILES + blockIdx.y] = s;
    }
}

// ============================ LSE combine + final subtract ============================
__global__ void lse_reduce_kernel(const float* __restrict__ pmax, const float* __restrict__ psum,
                                  float* __restrict__ lse) {
    __shared__ float sm[256];
    __shared__ float ss[256];
    const int r = blockIdx.x, t = threadIdx.x;
    float m = (t < NTILES) ? pmax[(size_t)r * NTILES + t] : -1e30f;
    sm[t] = m;
    __syncthreads();
    for (int s = 128; s > 0; s >>= 1) {
        if (t < s) sm[t] = fmaxf(sm[t], sm[t + s]);
        __syncthreads();
    }
    float gmax = sm[0];
    float sv = (t < NTILES) ? psum[(size_t)r * NTILES + t] * __expf(pmax[(size_t)r * NTILES + t] - gmax) : 0.f;
    ss[t] = sv;
    __syncthreads();
    for (int s = 128; s > 0; s >>= 1) {
        if (t < s) ss[t] += ss[t + s];
        __syncthreads();
    }
    if (t == 0) lse[r] = gmax + logf(ss[0]);
}

__global__ void sub_lse_kernel(const __half* __restrict__ gl, float* __restrict__ out,
                               const float* __restrict__ lse) {
    int i = blockIdx.x * blockDim.x + threadIdx.x;
    if (i < H * (VOCAB / 8)) {
        uint4 raw = __ldcs((const uint4*)gl + i);
        float l = __ldg(&lse[i / (VOCAB / 8)]);
        __half2* hp = (__half2*)&raw;
        float2 f0 = __half22float2(hp[0]);
        float2 f1 = __half22float2(hp[1]);
        float2 f2 = __half22float2(hp[2]);
        float2 f3 = __half22float2(hp[3]);
        float4 o0 = make_float4(f0.x - l, f0.y - l, f1.x - l, f1.y - l);
        float4 o1 = make_float4(f2.x - l, f2.y - l, f3.x - l, f3.y - l);
        __stcs((float4*)out + i * 2,     o0);
        __stcs((float4*)out + i * 2 + 1, o1);
    }
}

// ============================ launch ============================
extern "C" void kernel_launch(void* const* d_in, const int* in_sizes, int n_in,
                              void* d_out, int out_size) {
    const float* hidden = (const float*)d_in[0];
    const float* Whh_l  = (const float*)d_in[1];
    const float* bih_l  = (const float*)d_in[2];
    const float* bhh_l  = (const float*)d_in[3];
    const float* Whh_r  = (const float*)d_in[4];
    const float* bih_r  = (const float*)d_in[5];
    const float* bhh_r  = (const float*)d_in[6];
    const float* Wout   = (const float*)d_in[7];
    const float* bout   = (const float*)d_in[8];
    (void)in_sizes; (void)n_in; (void)out_size;

    float *hbuf[2], *pmax, *psum, *lse;
    __nv_bfloat16 *hhi[2], *whi, *wb;
    __half* gl;
    cudaGetSymbolAddress((void**)&hbuf[0], g_hbuf0);
    cudaGetSymbolAddress((void**)&hbuf[1], g_hbuf1);
    cudaGetSymbolAddress((void**)&hhi[0],  g_hhi0);
    cudaGetSymbolAddress((void**)&hhi[1],  g_hhi1);
    cudaGetSymbolAddress((void**)&whi,     g_whi);
    cudaGetSymbolAddress((void**)&wb,      g_w_bf16);
    cudaGetSymbolAddress((void**)&gl,      g_logits);
    cudaGetSymbolAddress((void**)&pmax,    g_pmax);
    cudaGetSymbolAddress((void**)&psum,    g_psum);
    cudaGetSymbolAddress((void**)&lse,     g_lse);

    cudaFuncSetAttribute(logits_gemm_kernel, cudaFuncAttributeMaxDynamicSharedMemorySize, 98304);
    cudaFuncSetAttribute(tree_mma_fused,     cudaFuncAttributeMaxDynamicSharedMemorySize, 86016);
    cudaFuncSetAttribute(gemv_split_kernel<4>, cudaFuncAttributeMaxDynamicSharedMemorySize, 49152);
    cudaFuncSetAttribute(gemv_split_bf16<8>,  cudaFuncAttributeMaxDynamicSharedMemorySize, 34816);
    cudaFuncSetAttribute(gemv_split_bf16<16>, cudaFuncAttributeMaxDynamicSharedMemorySize, 69632);

    // side stream objects (created once)
    static cudaStream_t s2 = nullptr;
    static cudaEvent_t evFork = nullptr, evJoin = nullptr;
    if (!s2) {
        cudaStreamCreateWithFlags(&s2, cudaStreamNonBlocking);
        cudaEventCreateWithFlags(&evFork, cudaEventDisableTiming);
        cudaEventCreateWithFlags(&evJoin, cudaEventDisableTiming);
    }

    // depths 0-2: fp32 GEMV + background Whh->bf16 conversion
    for (int d = 0; d <= 2; ++d) {
        const float* in = (d == 0) ? hidden : hbuf[d & 1];
        int o = (d + 1) & 1;
        int NN = 1 << d;
        size_t shmem = (size_t)NN * 1024 * sizeof(float) + 8 * 3 * NN * sizeof(float);
        int conv_base4 = d * 524288;
        switch (d) {
        case 0: gemv_split_kernel<1><<<1024, 256, shmem>>>(in, Whh_l, bih_l, bhh_l, Whh_r, bih_r, bhh_r,
                 hbuf[o], hhi[o], whi, conv_base4); break;
        case 1: gemv_split_kernel<2><<<1024, 256, shmem>>>(in, Whh_l, bih_l, bhh_l, Whh_r, bih_r, bhh_r,
                 hbuf[o], hhi[o], whi, conv_base4); break;
        default: gemv_split_kernel<4><<<1024, 256, shmem>>>(in, Whh_l, bih_l, bhh_l, Whh_r, bih_r, bhh_r,
                 hbuf[o], hhi[o], whi, conv_base4); break;
        }
    }

    // depths 3-4: bf16-W GEMV (R13-measured-best routing)
    for (int d = 3; d <= 4; ++d) {
        const float* in = hbuf[d & 1];
        int o = (d + 1) & 1;
        int NN = 1 << d;
        size_t shmem = (size_t)NN * 1024 * sizeof(float) + 8 * 3 * NN * sizeof(float);
        if (d == 3) gemv_split_bf16<8><<<512, 256, shmem>>>(in, whi, bih_l, bhh_l, bih_r, bhh_r,
                                                            hbuf[o], hhi[o]);
        else        gemv_split_bf16<16><<<512, 256, shmem>>>(in, whi, bih_l, bhh_l, bih_r, bhh_r,
                                                             hbuf[o], hhi[o]);
    }

    // fork: Wout fp32->bf16 overlaps depths 5-9
    cudaEventRecord(evFork, 0);
    cudaStreamWaitEvent(s2, evFork, 0);
    wout_conv_kernel<<<2048, 256, 0, s2>>>(Wout, wb);
    cudaEventRecord(evJoin, s2);

    // depths 5-9: single-product bf16 MMA (3-stage pipeline) with fused gating
    for (int d = 5; d <= 9; ++d) {
        int Nn = 1 << d;
        int ii = d & 1, o = (d + 1) & 1;
        dim3 mg((Nn + 127) / 128, 32, 2);
        tree_mma_fused<<<mg, 256, 86016>>>(hhi[ii], hbuf[ii], whi,
                                           bih_l, bhh_l, bih_r, bhh_r,
                                           hbuf[o], hhi[o], Nn);
    }

    // join conversion stream, then logits (fp16 scratch out)
    cudaStreamWaitEvent(0, evJoin, 0);
    dim3 ggrid(8, NTILES);
    logits_gemm_kernel<<<ggrid, 256, 98304>>>(hhi[0], wb, bout, gl, pmax, psum);

    lse_reduce_kernel<<<H, 256>>>(pmax, psum, lse);
    sub_lse_kernel<<<(H * (VOCAB / 8) + 255) / 256, 256>>>(gl, (float*)d_out, lse);
}